// round 11
// baseline (speedup 1.0000x reference)
#include <cuda_runtime.h>
#include <cstdint>

#define NBATCH 32
#define NPB (512*512)                 // 262144 pixels per image
#define VPB_BATCH (NPB/4)             // 65536 float4 per batch
#define GRID 256                      // total blocks (guaranteed co-resident)
#define BPB 8                         // passB blocks per batch
#define VPB (VPB_BATCH/BPB)           // 8192 float4 per block
#define NB 4096                       // bins: |residual| bits >> 19
#define BAND_MAX 1024
#define CNT_SHIFT 44
#define SUM_MASK ((1ull << CNT_SHIFT) - 1ull)
#define SAMPLE_STRIDE 64

__device__ unsigned long long d_hist[NBATCH][NB];   // only band bins touched
__device__ int   d_binlo[NBATCH], d_binhi[NBATCH];
__device__ float d_sumbelow[NBATCH];
__device__ int   d_cntbelow[NBATCH];
__device__ int   d_M[NBATCH];
__device__ float d_L, d_D;
__device__ unsigned d_cnt = 0;        // barrier arrive counter
__device__ unsigned d_gen = 0;        // barrier generation (monotonic across replays)

// ---- software grid barrier (all GRID blocks guaranteed resident) ----
__device__ __forceinline__ void grid_sync() {
    __syncthreads();
    if (threadIdx.x == 0) {
        unsigned g = *((volatile unsigned*)&d_gen);
        __threadfence();
        unsigned t = atomicAdd(&d_cnt, 1u);
        if (t == GRID - 1) {
            atomicExch(&d_cnt, 0u);
            __threadfence();
            *((volatile unsigned*)&d_gen) = g + 1;
        } else {
            while (*((volatile unsigned*)&d_gen) == g) __nanosleep(64);
            __threadfence();
        }
    }
    __syncthreads();
}

// exact per-bin float sum: s = cnt*lo(bin) + slow * 2^(E-150)
__device__ __forceinline__ float bin_sum(int bin, int cnt, unsigned long long slow) {
    if (cnt == 0) return 0.0f;
    float lo = __uint_as_float((unsigned)bin << 19);
    int E = bin >> 4;
    float w = ldexpf(1.0f, (E == 0) ? -149 : (E - 150));
    return (float)cnt * lo + (float)slow * w;
}

__global__ void __launch_bounds__(256, 2) k_fused(const float4* __restrict__ p,
                                                  const float4* __restrict__ t,
                                                  const int4*   __restrict__ m,
                                                  float* __restrict__ out) {
    __shared__ unsigned long long sh64[2048];        // 16KB: sample hist / band
    int* sh32 = (int*)sh64;                          // 4096 ints view
    __shared__ int s_nv;

    int bid = blockIdx.x, tid = threadIdx.x, lane = tid & 31, wid = tid >> 5;

    // ================= Phase 1: sample + bracket (blocks 0..31) =================
    if (bid < NBATCH) {
        int b = bid;
        for (int i = tid; i < NB; i += 256) sh32[i] = 0;
        if (tid == 0) {
            s_nv = 0;
            d_sumbelow[b] = 0.0f; d_cntbelow[b] = 0; d_M[b] = 0;
            if (b == 0) { d_L = 0.0f; d_D = 0.0f; }
        }
        __syncthreads();

        size_t base = (size_t)b * VPB_BATCH;
        int nv = 0;
        #pragma unroll
        for (int it = 0; it < (VPB_BATCH / SAMPLE_STRIDE) / 256; it++) {
            int i = tid + it * 256;
            size_t idx = base + (size_t)i * SAMPLE_STRIDE;
            float4 pv = p[idx]; float4 tv = t[idx]; int4 mv = m[idx];
            float dd[4] = { pv.x - tv.x, pv.y - tv.y, pv.z - tv.z, pv.w - tv.w };
            int   vv[4] = { mv.x > 0, mv.y > 0, mv.z > 0, mv.w > 0 };
            #pragma unroll
            for (int j = 0; j < 4; j++) {
                if (vv[j]) {
                    unsigned bits = __float_as_uint(dd[j]) & 0x7FFFFFFFu;
                    atomicAdd(&sh32[bits >> 19], 1);
                    nv++;
                }
            }
        }
        #pragma unroll
        for (int off = 16; off; off >>= 1) nv += __shfl_down_sync(0xFFFFFFFFu, nv, off);
        if (lane == 0) atomicAdd(&s_nv, nv);
        __syncthreads();

        if (tid < 32) {
            int n = s_nv;
            int binlo = 0, binhi = NB - 1;
            if (n > 16) {
                int ks = (int)((float)n * 0.8f);
                int delta = (int)(10.0f * sqrtf(0.16f * (float)n)) + 24;
                int rlo = ks - delta; if (rlo < 1) rlo = 1;
                int rhi = ks + delta;
                int blo = -1, bhi = -1, cum = 0;
                for (int bs = 0; bs < NB; bs += 32) {
                    int c = sh32[bs + lane];
                    int cs = c;
                    #pragma unroll
                    for (int off = 1; off < 32; off <<= 1) {
                        int x = __shfl_up_sync(0xFFFFFFFFu, cs, off);
                        if (lane >= off) cs += x;
                    }
                    int total = __shfl_sync(0xFFFFFFFFu, cs, 31);
                    if (blo < 0 && cum + total >= rlo) {
                        unsigned bal = __ballot_sync(0xFFFFFFFFu, cum + cs >= rlo);
                        blo = bs + (__ffs(bal) - 1);
                    }
                    if (bhi < 0 && cum + total >= rhi) {
                        unsigned bal = __ballot_sync(0xFFFFFFFFu, cum + cs >= rhi);
                        bhi = bs + (__ffs(bal) - 1);
                    }
                    cum += total;
                    if (blo >= 0 && bhi >= 0) break;
                }
                if (blo < 0) blo = NB - 1;
                if (bhi < 0) bhi = NB - 1;
                binlo = blo - 2; if (binlo < 0) binlo = 0;
                binhi = bhi + 2; if (binhi > NB - 1) binhi = NB - 1;
            }
            if (binhi > binlo + BAND_MAX - 1) binhi = binlo + BAND_MAX - 1;
            if (lane == 0) { d_binlo[b] = binlo; d_binhi[b] = binhi; }
        }
    }

    grid_sync();

    // ================= Phase 2: full pass (all blocks, BPB per batch) ===========
    {
        int b   = bid / BPB;
        int blk = bid % BPB;
        int BLO = d_binlo[b], BHI = d_binhi[b];

        for (int i = tid; i < BAND_MAX; i += 256) sh64[i] = 0ull;
        __syncthreads();

        size_t base = (size_t)b * VPB_BATCH + (size_t)blk * VPB;
        float s0 = 0.f, s1 = 0.f, s2 = 0.f, s3 = 0.f;
        int cnt = 0, Ml = 0;

        #pragma unroll 4
        for (int it = 0; it < VPB / 256; it++) {
            int i = tid + it * 256;
            float4 pv = p[base + i];
            float4 tv = t[base + i];
            int4   mv = m[base + i];
            unsigned b0 = __float_as_uint(pv.x - tv.x) & 0x7FFFFFFFu;
            unsigned b1 = __float_as_uint(pv.y - tv.y) & 0x7FFFFFFFu;
            unsigned b2 = __float_as_uint(pv.z - tv.z) & 0x7FFFFFFFu;
            unsigned b3 = __float_as_uint(pv.w - tv.w) & 0x7FFFFFFFu;
            if (mv.x > 0) { Ml++; int bin = (int)(b0 >> 19);
                if (bin < BLO) { s0 += __uint_as_float(b0); cnt++; }
                else if (bin <= BHI) atomicAdd(&sh64[bin - BLO], (1ull << CNT_SHIFT) | (unsigned long long)(b0 & 0x7FFFFu)); }
            if (mv.y > 0) { Ml++; int bin = (int)(b1 >> 19);
                if (bin < BLO) { s1 += __uint_as_float(b1); cnt++; }
                else if (bin <= BHI) atomicAdd(&sh64[bin - BLO], (1ull << CNT_SHIFT) | (unsigned long long)(b1 & 0x7FFFFu)); }
            if (mv.z > 0) { Ml++; int bin = (int)(b2 >> 19);
                if (bin < BLO) { s2 += __uint_as_float(b2); cnt++; }
                else if (bin <= BHI) atomicAdd(&sh64[bin - BLO], (1ull << CNT_SHIFT) | (unsigned long long)(b2 & 0x7FFFFu)); }
            if (mv.w > 0) { Ml++; int bin = (int)(b3 >> 19);
                if (bin < BLO) { s3 += __uint_as_float(b3); cnt++; }
                else if (bin <= BHI) atomicAdd(&sh64[bin - BLO], (1ull << CNT_SHIFT) | (unsigned long long)(b3 & 0x7FFFFu)); }
        }

        float s = (s0 + s1) + (s2 + s3);
        #pragma unroll
        for (int off = 16; off; off >>= 1) {
            s   += __shfl_down_sync(0xFFFFFFFFu, s, off);
            cnt += __shfl_down_sync(0xFFFFFFFFu, cnt, off);
            Ml  += __shfl_down_sync(0xFFFFFFFFu, Ml, off);
        }
        if (lane == 0) {
            atomicAdd(&d_sumbelow[b], s);
            atomicAdd(&d_cntbelow[b], cnt);
            atomicAdd(&d_M[b], Ml);
        }
        __syncthreads();

        int nband = BHI - BLO + 1;
        for (int i = tid; i < nband; i += 256) {
            unsigned long long v = sh64[i];
            if (v) atomicAdd(&d_hist[b][BLO + i], v);
        }
    }

    grid_sync();

    // ================= Phase 3: finalize per batch (blocks 0..31) ===============
    if (bid < NBATCH) {
        int b = bid;
        int BLO = d_binlo[b], BHI = d_binhi[b];
        int nband = BHI - BLO + 1;

        for (int i = tid; i < nband; i += 256) sh64[i] = d_hist[b][BLO + i];
        __syncthreads();

        if (wid > 0) {
            // warps 1-7: re-zero this batch's band for the next graph replay
            for (int i = tid - 32; i < nband; i += 224) d_hist[b][BLO + i] = 0ull;
        } else {
            int M = d_M[b];
            float div = (float)M * (1.0f - 0.2f);
            int k = (int)floorf(div);
            float loss = 0.0f;
            if (k > 0) {
                float below = d_sumbelow[b];
                int r1 = k - d_cntbelow[b];
                if (r1 <= 0) {
                    loss = below;                            // defensive (bracket low)
                } else {
                    int cum = 0; float acc = 0.0f; int done = 0;
                    for (int j0 = 0; j0 < nband; j0 += 32) {
                        int j = j0 + lane;
                        unsigned long long v = (j < nband) ? sh64[j] : 0ull;
                        int c = (int)(v >> CNT_SHIFT);
                        float sv = bin_sum(BLO + j, c, v & SUM_MASK);
                        int cs = c;
                        #pragma unroll
                        for (int off = 1; off < 32; off <<= 1) {
                            int x = __shfl_up_sync(0xFFFFFFFFu, cs, off);
                            if (lane >= off) cs += x;
                        }
                        int total = __shfl_sync(0xFFFFFFFFu, cs, 31);
                        if (cum + total >= r1) {
                            unsigned bal = __ballot_sync(0xFFFFFFFFu, cum + cs >= r1);
                            int l = __ffs(bal) - 1;
                            int excl = __shfl_sync(0xFFFFFFFFu, cs - c, l);
                            int r2 = r1 - (cum + excl);
                            float pv = (lane < l) ? sv : 0.0f;
                            #pragma unroll
                            for (int off = 16; off; off >>= 1)
                                pv += __shfl_xor_sync(0xFFFFFFFFu, pv, off);
                            int   cl = __shfl_sync(0xFFFFFFFFu, c, l);
                            float sl = __shfl_sync(0xFFFFFFFFu, sv, l);
                            float lo = __uint_as_float((unsigned)(BLO + j0 + l) << 19);
                            float mbar = sl / (float)cl;
                            float partial = (float)r2 * lo
                                          + (mbar - lo) * ((float)r2 * (float)r2) / (float)cl;
                            loss = below + acc + pv + partial;
                            done = 1;
                            break;
                        }
                        cum += total;
                        float cssum = sv;
                        #pragma unroll
                        for (int off = 16; off; off >>= 1)
                            cssum += __shfl_xor_sync(0xFFFFFFFFu, cssum, off);
                        acc += cssum;
                    }
                    if (!done) loss = below + acc;           // defensive (bracket high)
                }
            }
            if (lane == 0) {
                atomicAdd(&d_L, loss);
                atomicAdd(&d_D, div);
            }
        }
    }

    grid_sync();

    // ================= Phase 4: write result ====================================
    if (bid == 0 && tid == 0) {
        float D = d_D;
        out[0] = (D == 0.0f) ? 0.0f : d_L / fmaxf(D, 1e-30f);
    }
}

extern "C" void kernel_launch(void* const* d_in, const int* in_sizes, int n_in,
                              void* d_out, int out_size) {
    const float4* p = (const float4*)d_in[0];   // prediction f32 [32,512,512]
    const float4* t = (const float4*)d_in[1];   // target     f32 [32,512,512]
    const int4*   m = (const int4*)d_in[2];     // mask       i32 [32,512,512]
    float* out = (float*)d_out;

    k_fused<<<GRID, 256>>>(p, t, m, out);
}

// round 13
// speedup vs baseline: 1.2077x; 1.2077x over previous
#include <cuda_runtime.h>
#include <cstdint>

#define NBATCH 32
#define NPB (512*512)                 // 262144 pixels per image
#define VPB_BATCH (NPB/4)             // 65536 float4 per batch
#define BPB 64                        // main-pass blocks per batch
#define VPB (VPB_BATCH/BPB)           // 1024 float4 per block
#define NB 4096                       // bins: |residual| bits >> 19
#define BAND_MAX 1024
#define CNT_SHIFT 44
#define SUM_MASK ((1ull << CNT_SHIFT) - 1ull)
#define SAMPLE_STRIDE 128

__device__ unsigned long long d_hist[NBATCH][NB];   // only band bins touched
__device__ int   d_binlo[NBATCH], d_binhi[NBATCH];
__device__ float d_sumbelow[NBATCH];
__device__ int   d_cntbelow[NBATCH];
__device__ int   d_M[NBATCH];
__device__ unsigned d_done[NBATCH];                 // per-batch arrival tickets
__device__ unsigned d_alldone;                      // batch-finalizer ticket
__device__ float d_L, d_D;

// exact per-bin float sum: s = cnt*lo(bin) + slow * 2^(E-150)
__device__ __forceinline__ float bin_sum(int bin, int cnt, unsigned long long slow) {
    if (cnt == 0) return 0.0f;
    float lo = __uint_as_float((unsigned)bin << 19);
    int E = bin >> 4;
    float w = ldexpf(1.0f, (E == 0) ? -149 : (E - 150));
    return (float)cnt * lo + (float)slow * w;
}

// ---- pass A: 1/128 sample -> per-batch quantile bracket [BIN_LO, BIN_HI] ----
__global__ void __launch_bounds__(256) k_sample(const float4* __restrict__ p,
                                                const float4* __restrict__ t,
                                                const int4*   __restrict__ m) {
    __shared__ int sh[NB];
    __shared__ int s_nv;
    int b = blockIdx.x, tid = threadIdx.x, lane = tid & 31;
    for (int i = tid; i < NB; i += 256) sh[i] = 0;
    if (tid == 0) {
        s_nv = 0;
        d_sumbelow[b] = 0.0f; d_cntbelow[b] = 0; d_M[b] = 0;
        if (b == 0) { d_L = 0.0f; d_D = 0.0f; d_alldone = 0u; }
    }
    __syncthreads();

    size_t base = (size_t)b * VPB_BATCH;
    int nv = 0;
    #pragma unroll
    for (int it = 0; it < (VPB_BATCH / SAMPLE_STRIDE) / 256; it++) {
        int i = tid + it * 256;
        size_t idx = base + (size_t)i * SAMPLE_STRIDE;
        float4 pv = p[idx]; float4 tv = t[idx]; int4 mv = m[idx];
        float dd[4] = { pv.x - tv.x, pv.y - tv.y, pv.z - tv.z, pv.w - tv.w };
        int   vv[4] = { mv.x > 0, mv.y > 0, mv.z > 0, mv.w > 0 };
        #pragma unroll
        for (int j = 0; j < 4; j++) {
            if (vv[j]) {
                unsigned bits = __float_as_uint(dd[j]) & 0x7FFFFFFFu;
                atomicAdd(&sh[bits >> 19], 1);
                nv++;
            }
        }
    }
    #pragma unroll
    for (int off = 16; off; off >>= 1) nv += __shfl_down_sync(0xFFFFFFFFu, nv, off);
    if (lane == 0) atomicAdd(&s_nv, nv);
    __syncthreads();

    if (tid < 32) {
        int n = s_nv;
        int binlo = 0, binhi = NB - 1;
        if (n > 16) {
            int ks = (int)((float)n * 0.8f);
            int delta = (int)(10.0f * sqrtf(0.16f * (float)n)) + 24;
            int rlo = ks - delta; if (rlo < 1) rlo = 1;
            int rhi = ks + delta;
            int blo = -1, bhi = -1, cum = 0;
            for (int bs = 0; bs < NB; bs += 32) {
                int c = sh[bs + lane];
                int cs = c;
                #pragma unroll
                for (int off = 1; off < 32; off <<= 1) {
                    int x = __shfl_up_sync(0xFFFFFFFFu, cs, off);
                    if (lane >= off) cs += x;
                }
                int total = __shfl_sync(0xFFFFFFFFu, cs, 31);
                if (blo < 0 && cum + total >= rlo) {
                    unsigned bal = __ballot_sync(0xFFFFFFFFu, cum + cs >= rlo);
                    blo = bs + (__ffs(bal) - 1);
                }
                if (bhi < 0 && cum + total >= rhi) {
                    unsigned bal = __ballot_sync(0xFFFFFFFFu, cum + cs >= rhi);
                    bhi = bs + (__ffs(bal) - 1);
                }
                cum += total;
                if (blo >= 0 && bhi >= 0) break;
            }
            if (blo < 0) blo = NB - 1;
            if (bhi < 0) bhi = NB - 1;
            binlo = blo - 2; if (binlo < 0) binlo = 0;
            binhi = bhi + 2; if (binhi > NB - 1) binhi = NB - 1;
        }
        if (binhi > binlo + BAND_MAX - 1) binhi = binlo + BAND_MAX - 1;
        if (lane == 0) { d_binlo[b] = binlo; d_binhi[b] = binhi; }
    }
}

// ---- main pass: full read + per-batch last-block finalize + global last write ----
__global__ void __launch_bounds__(256) k_main(const float4* __restrict__ p,
                                              const float4* __restrict__ t,
                                              const int4*   __restrict__ m,
                                              float* __restrict__ out) {
    __shared__ unsigned long long sh[BAND_MAX];
    __shared__ unsigned s_last;
    int tid = threadIdx.x, lane = tid & 31, wid = tid >> 5;
    int b   = blockIdx.x / BPB;
    int blk = blockIdx.x % BPB;
    int BLO = d_binlo[b], BHI = d_binhi[b];
    int nband = BHI - BLO + 1;

    for (int i = tid; i < BAND_MAX; i += 256) sh[i] = 0ull;
    __syncthreads();

    size_t base = (size_t)b * VPB_BATCH + (size_t)blk * VPB;
    float s0 = 0.f, s1 = 0.f, s2 = 0.f, s3 = 0.f;
    int cnt = 0, Ml = 0;

    #pragma unroll
    for (int it = 0; it < VPB / 256; it++) {
        int i = tid + it * 256;
        float4 pv = p[base + i];
        float4 tv = t[base + i];
        int4   mv = m[base + i];
        unsigned b0 = __float_as_uint(pv.x - tv.x) & 0x7FFFFFFFu;
        unsigned b1 = __float_as_uint(pv.y - tv.y) & 0x7FFFFFFFu;
        unsigned b2 = __float_as_uint(pv.z - tv.z) & 0x7FFFFFFFu;
        unsigned b3 = __float_as_uint(pv.w - tv.w) & 0x7FFFFFFFu;
        if (mv.x > 0) { Ml++; int bin = (int)(b0 >> 19);
            if (bin < BLO) { s0 += __uint_as_float(b0); cnt++; }
            else if (bin <= BHI) atomicAdd(&sh[bin - BLO], (1ull << CNT_SHIFT) | (unsigned long long)(b0 & 0x7FFFFu)); }
        if (mv.y > 0) { Ml++; int bin = (int)(b1 >> 19);
            if (bin < BLO) { s1 += __uint_as_float(b1); cnt++; }
            else if (bin <= BHI) atomicAdd(&sh[bin - BLO], (1ull << CNT_SHIFT) | (unsigned long long)(b1 & 0x7FFFFu)); }
        if (mv.z > 0) { Ml++; int bin = (int)(b2 >> 19);
            if (bin < BLO) { s2 += __uint_as_float(b2); cnt++; }
            else if (bin <= BHI) atomicAdd(&sh[bin - BLO], (1ull << CNT_SHIFT) | (unsigned long long)(b2 & 0x7FFFFu)); }
        if (mv.w > 0) { Ml++; int bin = (int)(b3 >> 19);
            if (bin < BLO) { s3 += __uint_as_float(b3); cnt++; }
            else if (bin <= BHI) atomicAdd(&sh[bin - BLO], (1ull << CNT_SHIFT) | (unsigned long long)(b3 & 0x7FFFFu)); }
    }

    float s = (s0 + s1) + (s2 + s3);
    #pragma unroll
    for (int off = 16; off; off >>= 1) {
        s   += __shfl_down_sync(0xFFFFFFFFu, s, off);
        cnt += __shfl_down_sync(0xFFFFFFFFu, cnt, off);
        Ml  += __shfl_down_sync(0xFFFFFFFFu, Ml, off);
    }
    if (lane == 0) {
        atomicAdd(&d_sumbelow[b], s);
        atomicAdd(&d_cntbelow[b], cnt);
        atomicAdd(&d_M[b], Ml);
    }
    __syncthreads();

    // flush band to global
    for (int i = tid; i < nband; i += 256) {
        unsigned long long v = sh[i];
        if (v) atomicAdd(&d_hist[b][BLO + i], v);
    }
    __threadfence();           // make this thread's flush globally visible
    __syncthreads();

    // per-batch ticket: last arriving block finalizes this batch
    if (tid == 0) {
        unsigned old = atomicAdd(&d_done[b], 1u);
        s_last = (old == BPB - 1) ? 1u : 0u;
        if (s_last) d_done[b] = 0u;          // reset for next replay
    }
    __syncthreads();
    if (!s_last) return;

    // ---------- finalize batch b (one block) ----------
    for (int i = tid; i < nband; i += 256) sh[i] = __ldcg(&d_hist[b][BLO + i]);
    __syncthreads();

    if (wid > 0) {
        // warps 1-7: re-zero this batch's band for the next replay
        for (int i = tid - 32; i < nband; i += 224) d_hist[b][BLO + i] = 0ull;
    } else {
        int M = __ldcg(&d_M[b]);
        float div = (float)M * (1.0f - 0.2f);
        int k = (int)floorf(div);
        float loss = 0.0f;
        if (k > 0) {
            float below = __ldcg(&d_sumbelow[b]);
            int r1 = k - __ldcg(&d_cntbelow[b]);
            if (r1 <= 0) {
                loss = below;                          // defensive (bracket low)
            } else {
                int cum = 0; float acc = 0.0f; int done = 0;
                for (int j0 = 0; j0 < nband; j0 += 32) {
                    int j = j0 + lane;
                    unsigned long long v = (j < nband) ? sh[j] : 0ull;
                    int c = (int)(v >> CNT_SHIFT);
                    float sv = bin_sum(BLO + j, c, v & SUM_MASK);
                    int cs = c;
                    #pragma unroll
                    for (int off = 1; off < 32; off <<= 1) {
                        int x = __shfl_up_sync(0xFFFFFFFFu, cs, off);
                        if (lane >= off) cs += x;
                    }
                    int total = __shfl_sync(0xFFFFFFFFu, cs, 31);
                    if (cum + total >= r1) {
                        unsigned bal = __ballot_sync(0xFFFFFFFFu, cum + cs >= r1);
                        int l = __ffs(bal) - 1;
                        int excl = __shfl_sync(0xFFFFFFFFu, cs - c, l);
                        int r2 = r1 - (cum + excl);
                        float pv = (lane < l) ? sv : 0.0f;
                        #pragma unroll
                        for (int off = 16; off; off >>= 1)
                            pv += __shfl_xor_sync(0xFFFFFFFFu, pv, off);
                        int   cl = __shfl_sync(0xFFFFFFFFu, c, l);
                        float sl = __shfl_sync(0xFFFFFFFFu, sv, l);
                        float lo = __uint_as_float((unsigned)(BLO + j0 + l) << 19);
                        float mbar = sl / (float)cl;
                        float partial = (float)r2 * lo
                                      + (mbar - lo) * ((float)r2 * (float)r2) / (float)cl;
                        loss = below + acc + pv + partial;
                        done = 1;
                        break;
                    }
                    cum += total;
                    float cssum = sv;
                    #pragma unroll
                    for (int off = 16; off; off >>= 1)
                        cssum += __shfl_xor_sync(0xFFFFFFFFu, cssum, off);
                    acc += cssum;
                }
                if (!done) loss = below + acc;         // defensive (bracket high)
            }
        }
        if (lane == 0) {
            atomicAdd(&d_L, loss);
            atomicAdd(&d_D, div);
            __threadfence();
            // global ticket: last batch-finalizer writes the output
            unsigned old = atomicAdd(&d_alldone, 1u);
            if (old == NBATCH - 1) {
                float L = atomicAdd(&d_L, 0.0f);       // L2-coherent reads
                float D = atomicAdd(&d_D, 0.0f);
                out[0] = (D == 0.0f) ? 0.0f : L / fmaxf(D, 1e-30f);
                d_alldone = 0u;                        // reset for next replay
            }
        }
    }
}

extern "C" void kernel_launch(void* const* d_in, const int* in_sizes, int n_in,
                              void* d_out, int out_size) {
    const float4* p = (const float4*)d_in[0];   // prediction f32 [32,512,512]
    const float4* t = (const float4*)d_in[1];   // target     f32 [32,512,512]
    const int4*   m = (const int4*)d_in[2];     // mask       i32 [32,512,512]
    float* out = (float*)d_out;

    k_sample<<<NBATCH, 256>>>(p, t, m);
    k_main<<<NBATCH * BPB, 256>>>(p, t, m, out);
}